// round 1
// baseline (speedup 1.0000x reference)
#include <cuda_runtime.h>
#include <cuda_bf16.h>
#include <math.h>

// Problem constants (fixed shapes for this problem)
#define BB   256      // batch
#define TT   128      // time steps
#define EE   1024     // input dim
#define HH   1024     // hidden dim
#define EPSF 1e-6f

// ---------------- scratch (no cudaMalloc allowed) ----------------
__device__ float g_prem[(size_t)BB * TT * HH];   // 128 MB: pre-activation mobius_matvec(x_t, W_ih), all t
__device__ float g_mh  [2 * BB * HH];            // split-K partials of h @ W_hh
__device__ float g_h   [BB * HH];                // hidden state
__device__ float g_hn  [BB];                     // ||h|| per row (clamped >= EPS)

// ---------------- init ----------------
__global__ void init_kernel(float* h, float* hn) {
    int i = blockIdx.x * blockDim.x + threadIdx.x;
    if (i < BB * HH) h[i] = 0.0f;
    if (i < BB) hn[i] = EPSF;
}

// ---------------- SGEMM: C[z] = A[:, k0:k1] @ B[k0:k1, :]  (row-major) ------
// 64x64 tile, 256 threads, each thread 4x4. blockIdx.z selects K-chunk and
// writes to a separate partial buffer (C + z*M*N).
#define BM 64
#define BN 64
#define BK 16

__global__ __launch_bounds__(256) void sgemm_kernel(
    const float* __restrict__ A, const float* __restrict__ B,
    float* __restrict__ C, int M, int N, int K, int kChunk)
{
    int z  = blockIdx.z;
    int k0 = z * kChunk;
    int k1 = k0 + kChunk;   // shapes chosen so k1 <= K always
    float* Cz = C + (size_t)z * M * N;

    int rowTile = blockIdx.y * BM;
    int colTile = blockIdx.x * BN;

    __shared__ float As[BK][BM + 1];
    __shared__ float Bs[BK][BN];

    int tid = threadIdx.x;
    int ty = tid >> 4;        // 0..15
    int tx = tid & 15;        // 0..15

    float acc[4][4];
    #pragma unroll
    for (int i = 0; i < 4; i++)
        #pragma unroll
        for (int j = 0; j < 4; j++) acc[i][j] = 0.0f;

    for (int kk = k0; kk < k1; kk += BK) {
        #pragma unroll 4
        for (int i = tid; i < BM * BK; i += 256) {
            int r = i >> 4;           // /BK
            int c = i & (BK - 1);
            As[c][r] = A[(size_t)(rowTile + r) * K + kk + c];
        }
        #pragma unroll 4
        for (int i = tid; i < BK * BN; i += 256) {
            int r = i >> 6;           // /BN
            int c = i & (BN - 1);
            Bs[r][c] = B[(size_t)(kk + r) * N + colTile + c];
        }
        __syncthreads();

        #pragma unroll
        for (int k = 0; k < BK; k++) {
            float a[4], b[4];
            #pragma unroll
            for (int i = 0; i < 4; i++) a[i] = As[k][ty * 4 + i];
            #pragma unroll
            for (int j = 0; j < 4; j++) b[j] = Bs[k][tx * 4 + j];
            #pragma unroll
            for (int i = 0; i < 4; i++)
                #pragma unroll
                for (int j = 0; j < 4; j++)
                    acc[i][j] = fmaf(a[i], b[j], acc[i][j]);
        }
        __syncthreads();
    }

    #pragma unroll
    for (int i = 0; i < 4; i++)
        #pragma unroll
        for (int j = 0; j < 4; j++)
            Cz[(size_t)(rowTile + ty * 4 + i) * N + colTile + tx * 4 + j] = acc[i][j];
}

// ---------------- multi-value block reduction (256 threads) ----------------
template <int NV>
__device__ __forceinline__ void block_reduce_multi(float* vals, float* shbuf /* NV*8 */) {
    #pragma unroll
    for (int v = 0; v < NV; v++) {
        float x = vals[v];
        #pragma unroll
        for (int o = 16; o > 0; o >>= 1) x += __shfl_down_sync(0xffffffffu, x, o);
        if ((threadIdx.x & 31) == 0) shbuf[v * 8 + (threadIdx.x >> 5)] = x;
    }
    __syncthreads();
    if (threadIdx.x < NV) {
        float s = 0.0f;
        #pragma unroll
        for (int w = 0; w < 8; w++) s += shbuf[threadIdx.x * 8 + w];
        shbuf[threadIdx.x * 8] = s;
    }
    __syncthreads();
    #pragma unroll
    for (int v = 0; v < NV; v++) vals[v] = shbuf[v * 8];
}

__device__ __forceinline__ float artanh_clip(float x) {
    return atanhf(fminf(x, 1.0f - 1e-6f));   // x >= 0 here
}

// ---------------- prem rescale: prem = mobius_matvec scaling applied to X@W_ih
// one block per row (B*T rows). X row is contiguous (inp is [B,T,E] row-major).
__global__ __launch_bounds__(256) void prem_scale_kernel(
    const float* __restrict__ X, float* __restrict__ MX)
{
    __shared__ float sh[2 * 8];
    size_t r = blockIdx.x;
    const float* x = X + r * EE;
    float* mx = MX + r * HH;

    float x2 = 0.0f, m2 = 0.0f;
    #pragma unroll
    for (int j = 0; j < 4; j++) {
        int e = threadIdx.x + j * 256;
        float xv = x[e];  x2 += xv * xv;
        float mv = mx[e]; m2 += mv * mv;
    }
    float vals[2] = {x2, m2};
    block_reduce_multi<2>(vals, sh);

    float xn  = fmaxf(sqrtf(vals[0]), EPSF);
    float mxn = fmaxf(sqrtf(vals[1]), EPSF);
    float f = tanhf(mxn / xn * artanh_clip(xn)) / mxn;   // C = 1
    #pragma unroll
    for (int j = 0; j < 4; j++) {
        int e = threadIdx.x + j * 256;
        mx[e] *= f;
    }
}

// ---------------- fused recurrent step epilogue --------------------------
// Per row b:  u = mobius_matvec(h, W_hh) scaling of mh;  hid = mobius_add(u, b);
// s = mobius_add(prem_t, hid);  h_next = exp0(tanh(log0(s))).
// All mobius_add outputs are scalar-weighted linear combos, so only 6 dot
// products + 1 second-pass norm are needed.
__global__ __launch_bounds__(256) void step_kernel(
    const float* __restrict__ prem,   // g_prem base
    const float* __restrict__ bvec,   // b_h
    const float* __restrict__ mhbuf,  // g_mh (2 partials)
    float* __restrict__ hn_arr,       // g_hn
    float* __restrict__ hout,         // g_h or d_out on last step
    int t)
{
    __shared__ float sh[6 * 8];
    int b = blockIdx.x;
    const float* pr  = prem + ((size_t)b * TT + t) * HH;
    const float* mh0 = mhbuf + (size_t)b * HH;
    const float* mh1 = mh0 + (size_t)BB * HH;

    float p[4], m[4], bv[4];
    float s_m2 = 0, s_mb = 0, s_p2 = 0, s_pm = 0, s_pb = 0, s_b2 = 0;
    #pragma unroll
    for (int j = 0; j < 4; j++) {
        int e = threadIdx.x + j * 256;
        float mv = mh0[e] + mh1[e];
        float pv = pr[e];
        float bb = bvec[e];
        m[j] = mv; p[j] = pv; bv[j] = bb;
        s_m2 += mv * mv;  s_mb += mv * bb;  s_p2 += pv * pv;
        s_pm += pv * mv;  s_pb += pv * bb;  s_b2 += bb * bb;
    }
    float vals[6] = {s_m2, s_mb, s_p2, s_pm, s_pb, s_b2};
    block_reduce_multi<6>(vals, sh);
    float m2 = vals[0], mb = vals[1], p2 = vals[2];
    float pm = vals[3], pb = vals[4], b2 = vals[5];

    float hn  = hn_arr[b];
    float mhn = fmaxf(sqrtf(m2), EPSF);
    // u = fu * mh   (mobius_matvec scaling, C=1)
    float fu = tanhf(mhn / hn * artanh_clip(hn)) / mhn;
    float u2 = fu * fu * m2;
    float ub = fu * mb;

    // hid = mobius_add(u, b) = a1*u + c1*b
    float den1 = fmaxf(1.0f + 2.0f * ub + u2 * b2, EPSF);
    float a1 = (1.0f + 2.0f * ub + b2) / den1;
    float c1 = (1.0f - u2) / den1;
    float hid2 = a1 * a1 * u2 + 2.0f * a1 * c1 * ub + c1 * c1 * b2;
    float ph   = a1 * fu * pm + c1 * pb;          // dot(prem, hid)

    // s = mobius_add(prem, hid) = q1*prem + q2*hid
    float den2 = fmaxf(1.0f + 2.0f * ph + p2 * hid2, EPSF);
    float q1 = (1.0f + 2.0f * ph + hid2) / den2;
    float q2 = (1.0f - p2) / den2;
    float s2 = q1 * q1 * p2 + q2 * q2 * hid2 + 2.0f * q1 * q2 * ph;
    float sn = fmaxf(sqrtf(s2), EPSF);
    float g  = artanh_clip(sn) / sn;              // log0 scaling

    float cm = q2 * a1 * fu;                      // coeff of mh in s
    float cb = q2 * c1;                           // coeff of b in s

    float v[4]; float s_v2 = 0.0f;
    #pragma unroll
    for (int j = 0; j < 4; j++) {
        float sv = q1 * p[j] + cm * m[j] + cb * bv[j];
        float vv = tanhf(g * sv);
        v[j] = vv; s_v2 += vv * vv;
    }
    __syncthreads();                              // protect sh reuse
    float vv2[1] = {s_v2};
    block_reduce_multi<1>(vv2, sh);
    float vn = fmaxf(sqrtf(vv2[0]), EPSF);
    float k  = tanhf(vn) / vn;                    // exp0 scaling

    #pragma unroll
    for (int j = 0; j < 4; j++)
        hout[(size_t)b * HH + threadIdx.x + j * 256] = k * v[j];
    if (threadIdx.x == 0)
        hn_arr[b] = fmaxf(tanhf(vn), EPSF);       // ||h_next|| analytically
}

// ---------------- launch ----------------
extern "C" void kernel_launch(void* const* d_in, const int* in_sizes, int n_in,
                              void* d_out, int out_size)
{
    const float* inp  = (const float*)d_in[0];   // [B,T,E]
    const float* W_ih = (const float*)d_in[1];   // [E,H]
    const float* W_hh = (const float*)d_in[2];   // [H,H]
    const float* b_h  = (const float*)d_in[3];   // [H]
    float* out = (float*)d_out;                  // [B,H]

    float *prem, *mh, *h, *hn;
    cudaGetSymbolAddress((void**)&prem, g_prem);
    cudaGetSymbolAddress((void**)&mh,   g_mh);
    cudaGetSymbolAddress((void**)&h,    g_h);
    cudaGetSymbolAddress((void**)&hn,   g_hn);

    // init h = 0, hn = EPS
    init_kernel<<<(BB * HH + 255) / 256, 256>>>(h, hn);

    // precompute MX = X @ W_ih over all B*T rows, then apply mobius_matvec scale
    {
        dim3 grid(HH / BN, (BB * TT) / BM, 1);
        sgemm_kernel<<<grid, 256>>>(inp, W_ih, prem, BB * TT, HH, EE, EE);
        prem_scale_kernel<<<BB * TT, 256>>>(inp, prem);
    }

    // recurrence
    for (int t = 0; t < TT; t++) {
        dim3 grid(HH / BN, BB / BM, 2);                   // split-K = 2 -> 128 blocks
        sgemm_kernel<<<grid, 256>>>(h, W_hh, mh, BB, HH, HH, HH / 2);
        float* hout = (t == TT - 1) ? out : h;
        step_kernel<<<BB, 256>>>(prem, b_h, mh, hn, hout, t);
    }
}

// round 4
// speedup vs baseline: 2.9557x; 2.9557x over previous
#include <cuda_runtime.h>
#include <cuda_bf16.h>
#include <math.h>
#include <stdint.h>

// ---------------- problem constants ----------------
#define BB   256      // batch
#define TT   128      // time steps
#define EE   1024     // input dim
#define HH   1024     // hidden dim
#define KP   3072     // split K' = 3*1024  (Ah*Bh + Ah*Bl + Al*Bh)
#define EPSF 1e-6f

// ---------------- scratch (__device__ globals; no cudaMalloc) ----------------
__device__ __nv_bfloat16 g_Xs  [(size_t)BB * TT * KP];  // X split [B*T, 3E]  (hi|hi|lo)
__device__ __nv_bfloat16 g_WihT[(size_t)HH * KP];       // W_ih^T split [H, 3E] (hi|lo|hi)
__device__ __nv_bfloat16 g_WhhT[(size_t)HH * KP];       // W_hh^T split [H, 3H] (hi|lo|hi)
__device__ __nv_bfloat16 g_hs  [(size_t)BB * KP];       // h split [B, 3H]     (hi|hi|lo)
__device__ float g_prem[(size_t)BB * TT * HH];          // mobius_matvec(x_t, W_ih), all t
__device__ float g_mh  [2 * (size_t)BB * HH];           // split-K partials of h @ W_hh
__device__ float g_h   [(size_t)BB * HH];               // fp32 h sink (except last step)
__device__ float g_hn  [BB];                            // ||h|| per row

// ---------------- small PTX helpers (all sm_80-level, base-target safe) ------
__device__ __forceinline__ uint32_t smem_u32(const void* p) {
    uint32_t a;
    asm("{ .reg .u64 t; cvta.to.shared.u64 t, %1; cvt.u32.u64 %0, t; }" : "=r"(a) : "l"(p));
    return a;
}
__device__ __forceinline__ void cpasync16(uint32_t s, const void* g) {
    asm volatile("cp.async.cg.shared.global [%0], [%1], 16;" :: "r"(s), "l"(g));
}
#define CP_COMMIT() asm volatile("cp.async.commit_group;" ::: "memory")
#define CP_WAIT1()  asm volatile("cp.async.wait_group 1;" ::: "memory")

__device__ __forceinline__ void ldsm_x4(uint32_t& r0, uint32_t& r1, uint32_t& r2, uint32_t& r3,
                                        uint32_t addr) {
    asm volatile("ldmatrix.sync.aligned.m8n8.x4.shared.b16 {%0,%1,%2,%3}, [%4];"
                 : "=r"(r0), "=r"(r1), "=r"(r2), "=r"(r3) : "r"(addr));
}
__device__ __forceinline__ void mma_bf16(float& d0, float& d1, float& d2, float& d3,
                                         uint32_t a0, uint32_t a1, uint32_t a2, uint32_t a3,
                                         uint32_t b0, uint32_t b1) {
    asm volatile(
        "mma.sync.aligned.m16n8k16.row.col.f32.bf16.bf16.f32 "
        "{%0,%1,%2,%3}, {%4,%5,%6,%7}, {%8,%9}, {%0,%1,%2,%3};"
        : "+f"(d0), "+f"(d1), "+f"(d2), "+f"(d3)
        : "r"(a0), "r"(a1), "r"(a2), "r"(a3), "r"(b0), "r"(b1));
}

// ---------------- init ----------------
__global__ void init_kernel(uint32_t* hs_u32, float* hn) {
    int i = blockIdx.x * blockDim.x + threadIdx.x;
    if (i < (int)((size_t)BB * KP / 2)) hs_u32[i] = 0u;
    if (i < BB) hn[i] = EPSF;
}

// ---------------- fp32 -> split bf16 for X:  (hi | hi | lo) ----------------
__global__ __launch_bounds__(256) void splitX_kernel(const float* __restrict__ X,
                                                     __nv_bfloat16* __restrict__ Xs) {
    size_t idx = (size_t)blockIdx.x * blockDim.x + threadIdx.x;
    if (idx >= (size_t)BB * TT * EE) return;
    size_t r = idx / EE;
    size_t c = idx - r * EE;
    float v = X[idx];
    __nv_bfloat16 hi = __float2bfloat16(v);
    __nv_bfloat16 lo = __float2bfloat16(v - __bfloat162float(hi));
    __nv_bfloat16* row = Xs + r * KP;
    row[c] = hi;
    row[EE + c] = hi;
    row[2 * EE + c] = lo;
}

// ---------------- W [K,N] fp32 -> Wt [N, 3K] bf16 split (hi|lo|hi), transposed --
__global__ __launch_bounds__(256) void splitWT_kernel(const float* __restrict__ W,
                                                      __nv_bfloat16* __restrict__ Wt) {
    __shared__ float tile[32][33];
    int n0 = blockIdx.x * 32;
    int k0 = blockIdx.y * 32;
    int tx = threadIdx.x & 31;
    int ty = threadIdx.x >> 5;
    #pragma unroll
    for (int i = 0; i < 32; i += 8)
        tile[ty + i][tx] = W[(size_t)(k0 + ty + i) * HH + n0 + tx];
    __syncthreads();
    #pragma unroll
    for (int i = 0; i < 32; i += 8) {
        float v = tile[tx][ty + i];          // = W[k0+tx][n0+ty+i]
        int n = n0 + ty + i;
        int k = k0 + tx;
        __nv_bfloat16 hi = __float2bfloat16(v);
        __nv_bfloat16 lo = __float2bfloat16(v - __bfloat162float(hi));
        __nv_bfloat16* row = Wt + (size_t)n * KP;
        row[k] = hi;
        row[HH + k] = lo;
        row[2 * HH + k] = hi;
    }
}

// ---------------- bf16 HMMA GEMM: C[M,N] = A[M,K'] @ Bt[N,K']^T ----------------
// 2-stage cp.async pipeline, BK=64 (128B smem rows, chunk^row swizzle),
// ldmatrix.x4 for A and B, m16n8k16 bf16 mma with fp32 accum.
// blockIdx.z selects a K' half (split-K) and writes to C + z*M*N.
#define GEMM_BK 64

template <int BM, int BN, int NWM, int NWN>
__global__ void __launch_bounds__(32 * NWM * NWN, (BM >= 128) ? 2 : 1)
gemm_mma_kernel(const __nv_bfloat16* __restrict__ A,
                const __nv_bfloat16* __restrict__ B,
                float* __restrict__ C, int M, int N, int kChunk)
{
    constexpr int NTHR   = 32 * NWM * NWN;
    constexpr int WARP_M = BM / NWM;          // 64 or 32
    constexpr int WARP_N = BN / NWN;          // 32
    constexpr int MT  = WARP_M / 16;          // A m-tiles per warp
    constexpr int NT8 = WARP_N / 8;           // 8-wide n-tiles per warp
    constexpr int NX4 = NT8 / 2;              // B ldmatrix.x4 per k16 step
    constexpr int ABYTES = BM * 128;          // one A stage
    constexpr int BBYTES = BN * 128;

    extern __shared__ char smem[];
    uint32_t sbase = smem_u32(smem);
    // layout: [A0][B0][A1][B1]
    uint32_t sA[2], sB[2];
    sA[0] = sbase;                 sB[0] = sbase + ABYTES;
    sA[1] = sbase + ABYTES + BBYTES; sB[1] = sA[1] + ABYTES;

    int tid  = threadIdx.x;
    int warp = tid >> 5;
    int lane = tid & 31;
    int wm = warp % NWM;
    int wn = warp / NWM;

    int z = blockIdx.z;
    size_t rowTile = (size_t)blockIdx.y * BM;
    size_t colTile = (size_t)blockIdx.x * BN;
    const __nv_bfloat16* Abase = A + rowTile * KP + (size_t)z * kChunk;
    const __nv_bfloat16* Bbase = B + colTile * KP + (size_t)z * kChunk;
    float* Cz = C + (size_t)z * M * N;

    float acc[MT][NT8][4];
    #pragma unroll
    for (int i = 0; i < MT; i++)
        #pragma unroll
        for (int j = 0; j < NT8; j++)
            #pragma unroll
            for (int e = 0; e < 4; e++) acc[i][j][e] = 0.0f;

    const int nch = kChunk / GEMM_BK;

    // ---- stage loader (cp.async) ----
    auto load_stage = [&](int st, int c) {
        const __nv_bfloat16* Ag = Abase + (size_t)c * GEMM_BK;
        const __nv_bfloat16* Bg = Bbase + (size_t)c * GEMM_BK;
        #pragma unroll
        for (int u = tid; u < BM * 8; u += NTHR) {
            int row = u >> 3, ch = u & 7;
            uint32_t phys = (uint32_t)(row * 128 + ((ch ^ (row & 7)) << 4));
            cpasync16(sA[st] + phys, Ag + (size_t)row * KP + ch * 8);
        }
        #pragma unroll
        for (int u = tid; u < BN * 8; u += NTHR) {
            int row = u >> 3, ch = u & 7;
            uint32_t phys = (uint32_t)(row * 128 + ((ch ^ (row & 7)) << 4));
            cpasync16(sB[st] + phys, Bg + (size_t)row * KP + ch * 8);
        }
    };

    load_stage(0, 0);
    CP_COMMIT();

    for (int c = 0; c < nch; c++) {
        if (c + 1 < nch) load_stage((c + 1) & 1, c + 1);
        CP_COMMIT();
        CP_WAIT1();                // stage c resident
        __syncthreads();

        uint32_t a = sA[c & 1], b = sB[c & 1];
        #pragma unroll
        for (int s = 0; s < 4; s++) {        // 4 x k16 per 64-chunk
            uint32_t af[MT][4];
            #pragma unroll
            for (int i = 0; i < MT; i++) {
                int row = wm * WARP_M + i * 16 + (lane & 15);
                int ch  = 2 * s + (lane >> 4);
                uint32_t addr = a + row * 128 + ((ch ^ (row & 7)) << 4);
                ldsm_x4(af[i][0], af[i][1], af[i][2], af[i][3], addr);
            }
            uint32_t bf[NX4][4];
            #pragma unroll
            for (int j = 0; j < NX4; j++) {
                int row = wn * WARP_N + j * 16 + (lane & 7) + ((lane >> 4) << 3);
                int ch  = 2 * s + ((lane >> 3) & 1);
                uint32_t addr = b + row * 128 + ((ch ^ (row & 7)) << 4);
                ldsm_x4(bf[j][0], bf[j][1], bf[j][2], bf[j][3], addr);
            }
            #pragma unroll
            for (int i = 0; i < MT; i++)
                #pragma unroll
                for (int nj = 0; nj < NT8; nj++) {
                    uint32_t b0 = bf[nj >> 1][(nj & 1) * 2];
                    uint32_t b1 = bf[nj >> 1][(nj & 1) * 2 + 1];
                    mma_bf16(acc[i][nj][0], acc[i][nj][1], acc[i][nj][2], acc[i][nj][3],
                             af[i][0], af[i][1], af[i][2], af[i][3], b0, b1);
                }
        }
        __syncthreads();
    }

    // ---- epilogue ----
    int g = lane >> 2, t4 = lane & 3;
    #pragma unroll
    for (int i = 0; i < MT; i++) {
        #pragma unroll
        for (int nj = 0; nj < NT8; nj++) {
            size_t row0 = rowTile + wm * WARP_M + i * 16 + g;
            size_t col  = colTile + wn * WARP_N + nj * 8 + 2 * t4;
            float2 v0 = make_float2(acc[i][nj][0], acc[i][nj][1]);
            float2 v1 = make_float2(acc[i][nj][2], acc[i][nj][3]);
            *reinterpret_cast<float2*>(&Cz[row0 * N + col])       = v0;
            *reinterpret_cast<float2*>(&Cz[(row0 + 8) * N + col]) = v1;
        }
    }
}

// ---------------- multi-value block reduction (256 threads) ----------------
template <int NV>
__device__ __forceinline__ void block_reduce_multi(float* vals, float* shbuf) {
    #pragma unroll
    for (int v = 0; v < NV; v++) {
        float x = vals[v];
        #pragma unroll
        for (int o = 16; o > 0; o >>= 1) x += __shfl_down_sync(0xffffffffu, x, o);
        if ((threadIdx.x & 31) == 0) shbuf[v * 8 + (threadIdx.x >> 5)] = x;
    }
    __syncthreads();
    if (threadIdx.x < NV) {
        float s = 0.0f;
        #pragma unroll
        for (int w = 0; w < 8; w++) s += shbuf[threadIdx.x * 8 + w];
        shbuf[threadIdx.x * 8] = s;
    }
    __syncthreads();
    #pragma unroll
    for (int v = 0; v < NV; v++) vals[v] = shbuf[v * 8];
}

__device__ __forceinline__ float artanh_clip(float x) {
    return atanhf(fminf(x, 1.0f - 1e-6f));
}

// ---------------- prem rescale (mobius_matvec scaling) ----------------
__global__ __launch_bounds__(256) void prem_scale_kernel(
    const float* __restrict__ X, float* __restrict__ MX)
{
    __shared__ float sh[2 * 8];
    size_t r = blockIdx.x;
    const float* x = X + r * EE;
    float* mx = MX + r * HH;

    float x2 = 0.0f, m2 = 0.0f;
    #pragma unroll
    for (int j = 0; j < 4; j++) {
        int e = threadIdx.x + j * 256;
        float xv = x[e];  x2 += xv * xv;
        float mv = mx[e]; m2 += mv * mv;
    }
    float vals[2] = {x2, m2};
    block_reduce_multi<2>(vals, sh);

    float xn  = fmaxf(sqrtf(vals[0]), EPSF);
    float mxn = fmaxf(sqrtf(vals[1]), EPSF);
    float f = tanhf(mxn / xn * artanh_clip(xn)) / mxn;   // C = 1
    #pragma unroll
    for (int j = 0; j < 4; j++) {
        int e = threadIdx.x + j * 256;
        mx[e] *= f;
    }
}

// ---------------- fused recurrent step epilogue ----------------
__global__ __launch_bounds__(256) void step_kernel(
    const float* __restrict__ prem,
    const float* __restrict__ bvec,
    const float* __restrict__ mhbuf,  // 2 split-K partials [B,H]
    float* __restrict__ hn_arr,
    __nv_bfloat16* __restrict__ hs,   // [B, 3H] split hidden for next GEMM
    float* __restrict__ hout,         // sink / d_out on last step
    int t)
{
    __shared__ float sh[6 * 8];
    int b = blockIdx.x;
    const float* pr  = prem + ((size_t)b * TT + t) * HH;
    const float* mh0 = mhbuf + (size_t)b * HH;
    const float* mh1 = mh0 + (size_t)BB * HH;

    float p[4], m[4], bv[4];
    float s_m2 = 0, s_mb = 0, s_p2 = 0, s_pm = 0, s_pb = 0, s_b2 = 0;
    #pragma unroll
    for (int j = 0; j < 4; j++) {
        int e = threadIdx.x + j * 256;
        float mv = mh0[e] + mh1[e];
        float pv = pr[e];
        float bb = bvec[e];
        m[j] = mv; p[j] = pv; bv[j] = bb;
        s_m2 += mv * mv;  s_mb += mv * bb;  s_p2 += pv * pv;
        s_pm += pv * mv;  s_pb += pv * bb;  s_b2 += bb * bb;
    }
    float vals[6] = {s_m2, s_mb, s_p2, s_pm, s_pb, s_b2};
    block_reduce_multi<6>(vals, sh);
    float m2 = vals[0], mb = vals[1], p2 = vals[2];
    float pm = vals[3], pb = vals[4], b2 = vals[5];

    float hn  = hn_arr[b];
    float mhn = fmaxf(sqrtf(m2), EPSF);
    float fu = tanhf(mhn / hn * artanh_clip(hn)) / mhn;   // mobius_matvec scale
    float u2 = fu * fu * m2;
    float ub = fu * mb;

    float den1 = fmaxf(1.0f + 2.0f * ub + u2 * b2, EPSF);
    float a1 = (1.0f + 2.0f * ub + b2) / den1;
    float c1 = (1.0f - u2) / den1;
    float hid2 = a1 * a1 * u2 + 2.0f * a1 * c1 * ub + c1 * c1 * b2;
    float ph   = a1 * fu * pm + c1 * pb;

    float den2 = fmaxf(1.0f + 2.0f * ph + p2 * hid2, EPSF);
    float q1 = (1.0f + 2.0f * ph + hid2) / den2;
    float q2 = (1.0f - p2) / den2;
    float s2 = q1 * q1 * p2 + q2 * q2 * hid2 + 2.0f * q1 * q2 * ph;
    float sn = fmaxf(sqrtf(s2), EPSF);
    float g  = artanh_clip(sn) / sn;

    float cm = q2 * a1 * fu;
    float cb = q2 * c1;

    float v[4]; float s_v2 = 0.0f;
    #pragma unroll
    for (int j = 0; j < 4; j++) {
        float sv = q1 * p[j] + cm * m[j] + cb * bv[j];
        float vv = tanhf(g * sv);
        v[j] = vv; s_v2 += vv * vv;
    }
    __syncthreads();
    float vv2[1] = {s_v2};
    block_reduce_multi<1>(vv2, sh);
    float vn = fmaxf(sqrtf(vv2[0]), EPSF);
    float k  = tanhf(vn) / vn;

    __nv_bfloat16* hrow = hs + (size_t)b * KP;
    #pragma unroll
    for (int j = 0; j < 4; j++) {
        int e = threadIdx.x + j * 256;
        float hv = k * v[j];
        hout[(size_t)b * HH + e] = hv;
        __nv_bfloat16 hi = __float2bfloat16(hv);
        __nv_bfloat16 lo = __float2bfloat16(hv - __bfloat162float(hi));
        hrow[e] = hi;                 // Ah
        hrow[HH + e] = hi;            // Ah
        hrow[2 * HH + e] = lo;        // Al
    }
    if (threadIdx.x == 0)
        hn_arr[b] = fmaxf(tanhf(vn), EPSF);
}

// ---------------- launch ----------------
extern "C" void kernel_launch(void* const* d_in, const int* in_sizes, int n_in,
                              void* d_out, int out_size)
{
    const float* inp  = (const float*)d_in[0];   // [B,T,E]
    const float* W_ih = (const float*)d_in[1];   // [E,H]
    const float* W_hh = (const float*)d_in[2];   // [H,H]
    const float* b_h  = (const float*)d_in[3];   // [H]
    float* out = (float*)d_out;                  // [B,H]

    __nv_bfloat16 *Xs, *WihT, *WhhT, *hs;
    float *prem, *mh, *h, *hn;
    cudaGetSymbolAddress((void**)&Xs,   g_Xs);
    cudaGetSymbolAddress((void**)&WihT, g_WihT);
    cudaGetSymbolAddress((void**)&WhhT, g_WhhT);
    cudaGetSymbolAddress((void**)&hs,   g_hs);
    cudaGetSymbolAddress((void**)&prem, g_prem);
    cudaGetSymbolAddress((void**)&mh,   g_mh);
    cudaGetSymbolAddress((void**)&h,    g_h);
    cudaGetSymbolAddress((void**)&hn,   g_hn);

    // smem: big = (128+128)*128*2 = 64KB ; small = (64+64)*128*2 = 32KB
    const int SMEM_BIG   = (128 + 128) * 128 * 2;
    const int SMEM_SMALL = (64 + 64) * 128 * 2;
    cudaFuncSetAttribute(gemm_mma_kernel<128, 128, 2, 4>,
                         cudaFuncAttributeMaxDynamicSharedMemorySize, SMEM_BIG);
    cudaFuncSetAttribute(gemm_mma_kernel<64, 64, 2, 2>,
                         cudaFuncAttributeMaxDynamicSharedMemorySize, SMEM_SMALL);

    // init split hidden = 0, hn = EPS
    {
        int n = (int)((size_t)BB * KP / 2);
        init_kernel<<<(n + 255) / 256, 256>>>((uint32_t*)hs, hn);
    }

    // prep: split/transpose weights, split X
    {
        dim3 gw(HH / 32, HH / 32);
        splitWT_kernel<<<gw, 256>>>(W_ih, WihT);
        splitWT_kernel<<<gw, 256>>>(W_hh, WhhT);
        size_t tot = (size_t)BB * TT * EE;
        splitX_kernel<<<(unsigned)((tot + 255) / 256), 256>>>(inp, Xs);
    }

    // big GEMM: prem = Xs @ WihT^T   [32768, 1024], full K' in one pass
    {
        dim3 grid(HH / 128, (BB * TT) / 128, 1);
        gemm_mma_kernel<128, 128, 2, 4><<<grid, 256, SMEM_BIG>>>(
            Xs, WihT, prem, BB * TT, HH, KP);
        prem_scale_kernel<<<BB * TT, 256>>>(inp, prem);
    }

    // recurrence: 64x64 tiles, split-K=2 -> 128 CTAs per step
    for (int t = 0; t < TT; t++) {
        dim3 grid(HH / 64, BB / 64, 2);
        gemm_mma_kernel<64, 64, 2, 2><<<grid, 128, SMEM_SMALL>>>(
            hs, WhhT, mh, BB, HH, KP / 2);
        float* hout = (t == TT - 1) ? out : h;
        step_kernel<<<BB, 256>>>(prem, b_h, mh, hn, hs, hout, t);
    }
}